// round 11
// baseline (speedup 1.0000x reference)
#include <cuda.h>
#include <cuda_runtime.h>
#include <cuda_fp16.h>
#include <cstdint>

// ---------------------------------------------------------------------------
// out[16384,3072] = x[16384,1024] @ W_eff^T + b
// W_eff = W_qkv; rows[0:1024) += W_b_q@W_a_q; rows[2048:3072) += W_b_v@W_a_v
// Fold LoRA into weights (fp32), convert x & W_eff to fp16, one GEMM.
// Persistent-CTA HMMA (mma.sync) GEMM, tile 256x128, 4-stage TMA pipeline.
// (Harness compiles at compute_103 virtual arch -> no tcgen05; HMMA path.)
// ---------------------------------------------------------------------------

#define M_TOTAL 16384
#define N_TOTAL 3072
#define K_TOTAL 1024
#define TILE_M 256
#define TILE_N 128
#define KCHUNK 64                        // fp16 elems per stage = 128B (SW128 row)
#define NKIT   (K_TOTAL / KCHUNK)        // 16
#define NST    4
#define A_STAGE 32768                    // TILE_M * 128B
#define B_STAGE 16384                    // TILE_N * 128B
#define NTILES  ((M_TOTAL / TILE_M) * (N_TOTAL / TILE_N))   // 64*24 = 1536
#define NBLK_N  (N_TOTAL / TILE_N)       // 24

#define SMEM_FULL  0                     // 4 x 8B
#define SMEM_EMPTY 32                    // 4 x 8B
#define SMEM_BIAS  128                   // 3072 floats = 12288 B
#define SMEM_A     13312                 // 1024-aligned
#define SMEM_B     (SMEM_A + NST * A_STAGE)      // 144384
#define SMEM_TOTAL (SMEM_B + NST * B_STAGE)      // 209920

// fp16 scratch (static device arrays are allowed; cudaMalloc is not)
__device__ __align__(1024) __half g_xh[(size_t)M_TOTAL * K_TOTAL];
__device__ __align__(1024) __half g_wh[(size_t)N_TOTAL * K_TOTAL];

// ---------------------------------------------------------------------------
// PTX helpers (all plain sm_90-level, compile at compute_103)
// ---------------------------------------------------------------------------
__device__ __forceinline__ uint32_t smem_u32(const void* p) {
    uint32_t a;
    asm("{ .reg .u64 t; cvta.to.shared.u64 t, %1; cvt.u32.u64 %0, t; }"
        : "=r"(a) : "l"(p));
    return a;
}
__device__ __forceinline__ uint32_t elect_one() {
    uint32_t pred;
    asm volatile(
        "{\n\t.reg .pred p;\n\telect.sync _|p, 0xFFFFFFFF;\n\t"
        "selp.b32 %0, 1, 0, p;\n\t}" : "=r"(pred));
    return pred;
}
__device__ __forceinline__ void mbar_init(uint32_t m, uint32_t c) {
    asm volatile("mbarrier.init.shared.b64 [%0], %1;" :: "r"(m), "r"(c) : "memory");
}
__device__ __forceinline__ void mbar_expect_tx(uint32_t m, uint32_t bytes) {
    asm volatile("mbarrier.arrive.expect_tx.shared.b64 _, [%0], %1;"
                 :: "r"(m), "r"(bytes) : "memory");
}
__device__ __forceinline__ void mbar_arrive(uint32_t m) {
    asm volatile("mbarrier.arrive.shared.b64 _, [%0];" :: "r"(m) : "memory");
}
__device__ __forceinline__ void mbar_wait(uint32_t m, uint32_t phase) {
    uint32_t done = 0;
    while (!done) {
        asm volatile(
            "{\n\t.reg .pred p;\n\t"
            "mbarrier.try_wait.parity.acquire.cta.shared::cta.b64 p, [%1], %2, 0x989680;\n\t"
            "selp.b32 %0, 1, 0, p;\n\t}"
            : "=r"(done) : "r"(m), "r"(phase) : "memory");
    }
}
__device__ __forceinline__ void tma_load_2d(uint32_t dst, const void* map,
                                            int cx, int cy, uint32_t mbar) {
    asm volatile(
        "cp.async.bulk.tensor.2d.shared::cta.global.tile.mbarrier::complete_tx::bytes "
        "[%0], [%1, {%2, %3}], [%4];"
        :: "r"(dst), "l"(map), "r"(cx), "r"(cy), "r"(mbar) : "memory");
}
__device__ __forceinline__ void ldsm_x4(uint32_t* r, uint32_t addr) {
    asm volatile("ldmatrix.sync.aligned.m8n8.x4.shared.b16 {%0,%1,%2,%3}, [%4];"
                 : "=r"(r[0]), "=r"(r[1]), "=r"(r[2]), "=r"(r[3]) : "r"(addr));
}
__device__ __forceinline__ void mma16816(float* c, const uint32_t* a,
                                         const uint32_t* b) {
    asm volatile(
        "mma.sync.aligned.m16n8k16.row.col.f32.f16.f16.f32 "
        "{%0,%1,%2,%3}, {%4,%5,%6,%7}, {%8,%9}, {%0,%1,%2,%3};"
        : "+f"(c[0]), "+f"(c[1]), "+f"(c[2]), "+f"(c[3])
        : "r"(a[0]), "r"(a[1]), "r"(a[2]), "r"(a[3]), "r"(b[0]), "r"(b[1]));
}

// ---------------------------------------------------------------------------
// Pre-kernel 1: x fp32 -> fp16 (8 elems/thread, 16B stores)
// ---------------------------------------------------------------------------
__device__ __forceinline__ uint32_t h2_bits(__half2 h) {
    return *reinterpret_cast<uint32_t*>(&h);
}

__global__ void conv_x_kernel(const float4* __restrict__ x) {
    int i = blockIdx.x * blockDim.x + threadIdx.x;   // M*K/8 threads
    float4 v0 = x[2 * i + 0];
    float4 v1 = x[2 * i + 1];
    uint4 o;
    o.x = h2_bits(__floats2half2_rn(v0.x, v0.y));
    o.y = h2_bits(__floats2half2_rn(v0.z, v0.w));
    o.z = h2_bits(__floats2half2_rn(v1.x, v1.y));
    o.w = h2_bits(__floats2half2_rn(v1.z, v1.w));
    reinterpret_cast<uint4*>(g_xh)[i] = o;
}

// ---------------------------------------------------------------------------
// Pre-kernel 2: W_eff = W_qkv + LoRA folds (fp32 math) -> fp16
// ---------------------------------------------------------------------------
__global__ void fuse_w_kernel(const float* __restrict__ Wqkv,
                              const float* __restrict__ Waq,
                              const float* __restrict__ Wbq,
                              const float* __restrict__ Wav,
                              const float* __restrict__ Wbv) {
    int idx = blockIdx.x * 256 + threadIdx.x;        // exactly N*K threads
    int n = idx >> 10;
    int k = idx & 1023;
    float acc = Wqkv[idx];
    if (n < 1024) {
#pragma unroll
        for (int r = 0; r < 16; ++r) acc += Wbq[n * 16 + r] * Waq[r * 1024 + k];
    } else if (n >= 2048) {
        int nn = n - 2048;
#pragma unroll
        for (int r = 0; r < 16; ++r) acc += Wbv[nn * 16 + r] * Wav[r * 1024 + k];
    }
    g_wh[idx] = __float2half_rn(acc);
}

// ---------------------------------------------------------------------------
// Persistent GEMM: 256x128 tile, 4-stage TMA pipeline,
// 17 warps (16 compute in 4x4 grid, warp tile 64x32; warp 16 = TMA producer)
// ---------------------------------------------------------------------------
__global__ void __launch_bounds__(544, 1)
gemm_f16_kernel(const __grid_constant__ CUtensorMap tmA,
                const __grid_constant__ CUtensorMap tmB,
                const float* __restrict__ bias,
                float* __restrict__ out) {
    extern __shared__ __align__(1024) char smem[];
    const uint32_t sb = smem_u32(smem);
    const int tid = threadIdx.x;
    const int wid = tid >> 5;
    const int lid = tid & 31;

    if (tid == 0) {
#pragma unroll
        for (int s = 0; s < NST; ++s) {
            mbar_init(sb + SMEM_FULL + s * 8, 1);
            mbar_init(sb + SMEM_EMPTY + s * 8, 16);
        }
    }
    float* sh_bias = reinterpret_cast<float*>(smem + SMEM_BIAS);
    for (int i = tid; i < N_TOTAL; i += 544) sh_bias[i] = bias[i];
    __syncthreads();

    // ---- producer: warp 16, one elected lane; streams all (tile, kt) chunks
    if (wid == 16) {
        if (elect_one()) {
            uint32_t pc = 0;
            for (int t = blockIdx.x; t < NTILES; t += gridDim.x) {
                const int m_base = (t / NBLK_N) * TILE_M;
                const int n_base = (t % NBLK_N) * TILE_N;
                for (int kt = 0; kt < NKIT; ++kt, ++pc) {
                    const int s = pc & (NST - 1);
                    const uint32_t ph = 1u ^ ((pc >> 2) & 1u);
                    mbar_wait(sb + SMEM_EMPTY + s * 8, ph);
                    mbar_expect_tx(sb + SMEM_FULL + s * 8, A_STAGE + B_STAGE);
                    tma_load_2d(sb + SMEM_A + s * A_STAGE, &tmA, kt * KCHUNK,
                                m_base, sb + SMEM_FULL + s * 8);
                    tma_load_2d(sb + SMEM_B + s * B_STAGE, &tmB, kt * KCHUNK,
                                n_base, sb + SMEM_FULL + s * 8);
                }
            }
        }
        return;
    }

    // ---- compute warps 0..15: warp grid 4(m) x 4(n), warp tile 64x32 ----
    const int warp_m = wid & 3;
    const int warp_n = wid >> 2;
    const int grp = lid >> 3;
    const int lr = lid & 7;

    // swizzled per-lane base offsets within a stage (j=0)
    uint32_t a_off[4];
#pragma unroll
    for (int mt = 0; mt < 4; ++mt) {
        int row = warp_m * 64 + mt * 16 + (grp & 1) * 8 + lr;
        int colb = (grp >> 1) * 16;
        a_off[mt] = row * 128 + (colb ^ ((row & 7) << 4));
    }
    uint32_t b_off[2];
#pragma unroll
    for (int ntp = 0; ntp < 2; ++ntp) {
        int nrow = warp_n * 32 + ntp * 16 + (grp >> 1) * 8 + lr;
        int colb = (grp & 1) * 16;
        b_off[ntp] = nrow * 128 + (colb ^ ((nrow & 7) << 4));
    }

    uint32_t cc = 0;   // global chunk counter (stage/phase bookkeeping)
    for (int t = blockIdx.x; t < NTILES; t += gridDim.x) {
        const int m_base = (t / NBLK_N) * TILE_M;
        const int n_base = (t % NBLK_N) * TILE_N;

        float acc[4][4][4];
#pragma unroll
        for (int mt = 0; mt < 4; ++mt)
#pragma unroll
            for (int nt = 0; nt < 4; ++nt)
#pragma unroll
                for (int q = 0; q < 4; ++q) acc[mt][nt][q] = 0.f;

        for (int kt = 0; kt < NKIT; ++kt, ++cc) {
            const int s = cc & (NST - 1);
            const uint32_t ph = (cc >> 2) & 1u;
            mbar_wait(sb + SMEM_FULL + s * 8, ph);
            const uint32_t aBase = sb + SMEM_A + s * A_STAGE;
            const uint32_t bBase = sb + SMEM_B + s * B_STAGE;
#pragma unroll
            for (int j = 0; j < 4; ++j) {
                const uint32_t jsw = j * 32;
                uint32_t a[4][4];
#pragma unroll
                for (int mt = 0; mt < 4; ++mt)
                    ldsm_x4(a[mt], aBase + (a_off[mt] ^ jsw));
#pragma unroll
                for (int ntp = 0; ntp < 2; ++ntp) {
                    uint32_t b[4];
                    ldsm_x4(b, bBase + (b_off[ntp] ^ jsw));
#pragma unroll
                    for (int mt = 0; mt < 4; ++mt) {
                        mma16816(acc[mt][2 * ntp + 0], a[mt], b + 0);
                        mma16816(acc[mt][2 * ntp + 1], a[mt], b + 2);
                    }
                }
            }
            __syncwarp();
            if (lid == 0) mbar_arrive(sb + SMEM_EMPTY + s * 8);
        }

        // epilogue: bias + stores (producer keeps prefetching next tile)
        float* obase = out + (size_t)(m_base + warp_m * 64) * N_TOTAL + n_base +
                       warp_n * 32;
        const int r0 = lid >> 2;
        const int c0 = (lid & 3) * 2;
        const int bcol = n_base + warp_n * 32;
#pragma unroll
        for (int mt = 0; mt < 4; ++mt) {
#pragma unroll
            for (int nt = 0; nt < 4; ++nt) {
                int col = nt * 8 + c0;
                float b0 = sh_bias[bcol + col];
                float b1 = sh_bias[bcol + col + 1];
                float2 v0 = {acc[mt][nt][0] + b0, acc[mt][nt][1] + b1};
                float2 v1 = {acc[mt][nt][2] + b0, acc[mt][nt][3] + b1};
                *reinterpret_cast<float2*>(
                    obase + (size_t)(mt * 16 + r0) * N_TOTAL + col) = v0;
                *reinterpret_cast<float2*>(
                    obase + (size_t)(mt * 16 + r0 + 8) * N_TOTAL + col) = v1;
            }
        }
    }
}

// ---------------------------------------------------------------------------
// Host
// ---------------------------------------------------------------------------
typedef CUresult (*PFN_encodeTiled)(
    CUtensorMap*, CUtensorMapDataType, cuuint32_t, void*,
    const cuuint64_t*, const cuuint64_t*, const cuuint32_t*, const cuuint32_t*,
    CUtensorMapInterleave, CUtensorMapSwizzle, CUtensorMapL2promotion,
    CUtensorMapFloatOOBfill);

extern "C" void kernel_launch(void* const* d_in, const int* in_sizes, int n_in,
                              void* d_out, int out_size) {
    const float* x    = (const float*)d_in[0];
    const float* Wqkv = (const float*)d_in[1];
    const float* bqkv = (const float*)d_in[2];
    const float* Waq  = (const float*)d_in[3];
    const float* Wbq  = (const float*)d_in[4];
    const float* Wav  = (const float*)d_in[5];
    const float* Wbv  = (const float*)d_in[6];
    float* out = (float*)d_out;

    conv_x_kernel<<<(M_TOTAL * K_TOTAL) / 8 / 256, 256>>>((const float4*)x);
    fuse_w_kernel<<<(N_TOTAL * K_TOTAL) / 256, 256>>>(Wqkv, Waq, Wbq, Wav, Wbv);

    void* xh_ptr = nullptr;
    void* wh_ptr = nullptr;
    cudaGetSymbolAddress(&xh_ptr, g_xh);
    cudaGetSymbolAddress(&wh_ptr, g_wh);

    void* fp = nullptr;
    cudaDriverEntryPointQueryResult qr;
#if CUDART_VERSION >= 12050
    cudaGetDriverEntryPointByVersion("cuTensorMapEncodeTiled", &fp, 12000,
                                     cudaEnableDefault, &qr);
#else
    cudaGetDriverEntryPoint("cuTensorMapEncodeTiled", &fp, cudaEnableDefault, &qr);
#endif
    PFN_encodeTiled encode = (PFN_encodeTiled)fp;

    CUtensorMap tmA, tmB;
    {
        cuuint64_t dims[2]   = {(cuuint64_t)K_TOTAL, (cuuint64_t)M_TOTAL};
        cuuint64_t stride[1] = {(cuuint64_t)K_TOTAL * 2};
        cuuint32_t box[2]    = {KCHUNK, TILE_M};
        cuuint32_t es[2]     = {1, 1};
        encode(&tmA, CU_TENSOR_MAP_DATA_TYPE_FLOAT16, 2, xh_ptr, dims, stride, box,
               es, CU_TENSOR_MAP_INTERLEAVE_NONE, CU_TENSOR_MAP_SWIZZLE_128B,
               CU_TENSOR_MAP_L2_PROMOTION_L2_128B, CU_TENSOR_MAP_FLOAT_OOB_FILL_NONE);
    }
    {
        cuuint64_t dims[2]   = {(cuuint64_t)K_TOTAL, (cuuint64_t)N_TOTAL};
        cuuint64_t stride[1] = {(cuuint64_t)K_TOTAL * 2};
        cuuint32_t box[2]    = {KCHUNK, TILE_N};
        cuuint32_t es[2]     = {1, 1};
        encode(&tmB, CU_TENSOR_MAP_DATA_TYPE_FLOAT16, 2, wh_ptr, dims, stride, box,
               es, CU_TENSOR_MAP_INTERLEAVE_NONE, CU_TENSOR_MAP_SWIZZLE_128B,
               CU_TENSOR_MAP_L2_PROMOTION_L2_128B, CU_TENSOR_MAP_FLOAT_OOB_FILL_NONE);
    }

    int nsm = 148;
    cudaDeviceGetAttribute(&nsm, cudaDevAttrMultiProcessorCount, 0);

    cudaFuncSetAttribute(gemm_f16_kernel,
                         cudaFuncAttributeMaxDynamicSharedMemorySize, SMEM_TOTAL);

    gemm_f16_kernel<<<nsm, 544, SMEM_TOTAL>>>(tmA, tmB, bqkv, out);
}

// round 12
// speedup vs baseline: 1.2395x; 1.2395x over previous
#include <cuda.h>
#include <cuda_runtime.h>
#include <cuda_fp16.h>
#include <cstdint>

// ---------------------------------------------------------------------------
// out[16384,3072] = x[16384,1024] @ W_eff^T + b
// W_eff = W_qkv; rows[0:1024) += W_b_q@W_a_q; rows[2048:3072) += W_b_v@W_a_v
// Fold LoRA into weights (fp32), convert x & W_eff to fp16, one GEMM.
// GEMM: known-good round-4 config — 128x128 tile, 2 CTAs/SM, 9 warps
// (8 compute, warp tile 32x64; 1 TMA producer), 3-stage TMA pipeline.
// Legacy mma.sync (HMMA) — measured at the HMMA issue ceiling.
// Pre-kernels merged into one launch (conv x->fp16 + LoRA-fold W->fp16).
// ---------------------------------------------------------------------------

#define M_TOTAL 16384
#define N_TOTAL 3072
#define K_TOTAL 1024
#define TILE_M 128
#define TILE_N 128
#define KCHUNK 64                       // fp16 elems per stage = 128B (SW128 row)
#define NKIT   (K_TOTAL / KCHUNK)       // 16
#define NST    3
#define A_STAGE 16384                   // TILE_M * 128B
#define B_STAGE 16384                   // TILE_N * 128B

#define SMEM_FULL  16                   // 3 x 8B
#define SMEM_EMPTY 48                   // 3 x 8B
#define SMEM_BIAS  128                  // 128 floats
#define SMEM_A     1024
#define SMEM_B     (SMEM_A + NST * A_STAGE)     // 50176
#define SMEM_TOTAL (SMEM_B + NST * B_STAGE)     // 99328 -> 2 CTAs/SM

// merged pre-kernel geometry
#define CONV_BLOCKS 8192                // (M*K/8)/256
#define FUSE_BLOCKS 3072                // (N*K/4)/256

// fp16 scratch (static device arrays are allowed; cudaMalloc is not)
__device__ __align__(1024) __half g_xh[(size_t)M_TOTAL * K_TOTAL];
__device__ __align__(1024) __half g_wh[(size_t)N_TOTAL * K_TOTAL];

// ---------------------------------------------------------------------------
// PTX helpers (all plain sm_90-level, compile at compute_103)
// ---------------------------------------------------------------------------
__device__ __forceinline__ uint32_t smem_u32(const void* p) {
    uint32_t a;
    asm("{ .reg .u64 t; cvta.to.shared.u64 t, %1; cvt.u32.u64 %0, t; }"
        : "=r"(a) : "l"(p));
    return a;
}
__device__ __forceinline__ uint32_t elect_one() {
    uint32_t pred;
    asm volatile(
        "{\n\t.reg .pred p;\n\telect.sync _|p, 0xFFFFFFFF;\n\t"
        "selp.b32 %0, 1, 0, p;\n\t}" : "=r"(pred));
    return pred;
}
__device__ __forceinline__ void mbar_init(uint32_t m, uint32_t c) {
    asm volatile("mbarrier.init.shared.b64 [%0], %1;" :: "r"(m), "r"(c) : "memory");
}
__device__ __forceinline__ void mbar_expect_tx(uint32_t m, uint32_t bytes) {
    asm volatile("mbarrier.arrive.expect_tx.shared.b64 _, [%0], %1;"
                 :: "r"(m), "r"(bytes) : "memory");
}
__device__ __forceinline__ void mbar_arrive(uint32_t m) {
    asm volatile("mbarrier.arrive.shared.b64 _, [%0];" :: "r"(m) : "memory");
}
__device__ __forceinline__ void mbar_wait(uint32_t m, uint32_t phase) {
    uint32_t done = 0;
    while (!done) {
        asm volatile(
            "{\n\t.reg .pred p;\n\t"
            "mbarrier.try_wait.parity.acquire.cta.shared::cta.b64 p, [%1], %2, 0x989680;\n\t"
            "selp.b32 %0, 1, 0, p;\n\t}"
            : "=r"(done) : "r"(m), "r"(phase) : "memory");
    }
}
__device__ __forceinline__ void tma_load_2d(uint32_t dst, const void* map,
                                            int cx, int cy, uint32_t mbar) {
    asm volatile(
        "cp.async.bulk.tensor.2d.shared::cta.global.tile.mbarrier::complete_tx::bytes "
        "[%0], [%1, {%2, %3}], [%4];"
        :: "r"(dst), "l"(map), "r"(cx), "r"(cy), "r"(mbar) : "memory");
}
__device__ __forceinline__ void ldsm_x4(uint32_t* r, uint32_t addr) {
    asm volatile("ldmatrix.sync.aligned.m8n8.x4.shared.b16 {%0,%1,%2,%3}, [%4];"
                 : "=r"(r[0]), "=r"(r[1]), "=r"(r[2]), "=r"(r[3]) : "r"(addr));
}
__device__ __forceinline__ void mma16816(float* c, const uint32_t* a,
                                         const uint32_t* b) {
    asm volatile(
        "mma.sync.aligned.m16n8k16.row.col.f32.f16.f16.f32 "
        "{%0,%1,%2,%3}, {%4,%5,%6,%7}, {%8,%9}, {%0,%1,%2,%3};"
        : "+f"(c[0]), "+f"(c[1]), "+f"(c[2]), "+f"(c[3])
        : "r"(a[0]), "r"(a[1]), "r"(a[2]), "r"(a[3]), "r"(b[0]), "r"(b[1]));
}

// ---------------------------------------------------------------------------
// Merged pre-kernel: blocks [0, CONV_BLOCKS) convert x fp32->fp16 (8/thread);
// blocks [CONV_BLOCKS, CONV_BLOCKS+FUSE_BLOCKS) build W_eff fp16 (4/thread).
// ---------------------------------------------------------------------------
__device__ __forceinline__ uint32_t h2_bits(__half2 h) {
    return *reinterpret_cast<uint32_t*>(&h);
}

__global__ void prep_kernel(const float4* __restrict__ x,
                            const float4* __restrict__ Wqkv4,
                            const float4* __restrict__ Waq4,
                            const float* __restrict__ Wbq,
                            const float4* __restrict__ Wav4,
                            const float* __restrict__ Wbv) {
    if (blockIdx.x < CONV_BLOCKS) {
        int i = blockIdx.x * 256 + threadIdx.x;      // M*K/8 threads
        float4 v0 = x[2 * i + 0];
        float4 v1 = x[2 * i + 1];
        uint4 o;
        o.x = h2_bits(__floats2half2_rn(v0.x, v0.y));
        o.y = h2_bits(__floats2half2_rn(v0.z, v0.w));
        o.z = h2_bits(__floats2half2_rn(v1.x, v1.y));
        o.w = h2_bits(__floats2half2_rn(v1.z, v1.w));
        reinterpret_cast<uint4*>(g_xh)[i] = o;
    } else {
        int idx4 = (blockIdx.x - CONV_BLOCKS) * 256 + threadIdx.x;  // N*K/4
        int n = idx4 >> 8;               // 256 float4 per row (K=1024)
        int k4 = idx4 & 255;
        float4 acc = Wqkv4[idx4];
        if (n < 1024) {
#pragma unroll
            for (int r = 0; r < 16; ++r) {
                float br = Wbq[n * 16 + r];
                float4 wa = Waq4[r * 256 + k4];
                acc.x += br * wa.x; acc.y += br * wa.y;
                acc.z += br * wa.z; acc.w += br * wa.w;
            }
        } else if (n >= 2048) {
            int nn = n - 2048;
#pragma unroll
            for (int r = 0; r < 16; ++r) {
                float br = Wbv[nn * 16 + r];
                float4 wa = Wav4[r * 256 + k4];
                acc.x += br * wa.x; acc.y += br * wa.y;
                acc.z += br * wa.z; acc.w += br * wa.w;
            }
        }
        uint2 o;
        o.x = h2_bits(__floats2half2_rn(acc.x, acc.y));
        o.y = h2_bits(__floats2half2_rn(acc.z, acc.w));
        reinterpret_cast<uint2*>(g_wh)[idx4] = o;
    }
}

// ---------------------------------------------------------------------------
// Main GEMM (known-good round-4 config): 128x128 tile, 3-stage TMA pipeline,
// 9 warps (8 compute in 4(m)x2(n) grid, warp tile 32x64; warp 8 = producer)
// grid = (N/128, M/128) = (24, 128), 2 CTAs/SM
// ---------------------------------------------------------------------------
__global__ void __launch_bounds__(288, 2)
gemm_f16_kernel(const __grid_constant__ CUtensorMap tmA,
                const __grid_constant__ CUtensorMap tmB,
                const float* __restrict__ bias,
                float* __restrict__ out) {
    extern __shared__ __align__(1024) char smem[];
    const uint32_t sb = smem_u32(smem);
    const int tid = threadIdx.x;
    const int wid = tid >> 5;
    const int lid = tid & 31;
    const int n_base = blockIdx.x * TILE_N;
    const int m_base = blockIdx.y * TILE_M;

    if (tid == 0) {
#pragma unroll
        for (int s = 0; s < NST; ++s) {
            mbar_init(sb + SMEM_FULL + s * 8, 1);
            mbar_init(sb + SMEM_EMPTY + s * 8, 8);
        }
    }
    float* sh_bias = reinterpret_cast<float*>(smem + SMEM_BIAS);
    if (tid < TILE_N) sh_bias[tid] = bias[n_base + tid];
    __syncthreads();

    // ---- producer: warp 8, one elected lane ----
    if (wid == 8) {
        if (elect_one()) {
            int s = 0, ph = 1;                      // phase 1: first waits pass
            for (int kt = 0; kt < NKIT; ++kt) {
                mbar_wait(sb + SMEM_EMPTY + s * 8, ph);
                mbar_expect_tx(sb + SMEM_FULL + s * 8, A_STAGE + B_STAGE);
                tma_load_2d(sb + SMEM_A + s * A_STAGE, &tmA, kt * KCHUNK, m_base,
                            sb + SMEM_FULL + s * 8);
                tma_load_2d(sb + SMEM_B + s * B_STAGE, &tmB, kt * KCHUNK, n_base,
                            sb + SMEM_FULL + s * 8);
                if (++s == NST) { s = 0; ph ^= 1; }
            }
        }
        return;
    }

    // ---- compute warps 0..7: warp grid 4(m) x 2(n), warp tile 32x64 ----
    const int warp_m = wid & 3;
    const int warp_n = wid >> 2;
    const int grp = lid >> 3;
    const int lr = lid & 7;

    float acc[2][8][4];
#pragma unroll
    for (int mt = 0; mt < 2; ++mt)
#pragma unroll
        for (int nt = 0; nt < 8; ++nt)
#pragma unroll
            for (int q = 0; q < 4; ++q) acc[mt][nt][q] = 0.f;

    // swizzled per-lane base offsets within a stage (j=0)
    uint32_t a_off[2];
#pragma unroll
    for (int mt = 0; mt < 2; ++mt) {
        int row = warp_m * 32 + mt * 16 + (grp & 1) * 8 + lr;
        int colb = (grp >> 1) * 16;
        a_off[mt] = row * 128 + (colb ^ ((row & 7) << 4));
    }
    uint32_t b_off[4];
#pragma unroll
    for (int ntp = 0; ntp < 4; ++ntp) {
        int nrow = warp_n * 64 + ntp * 16 + (grp >> 1) * 8 + lr;
        int colb = (grp & 1) * 16;
        b_off[ntp] = nrow * 128 + (colb ^ ((nrow & 7) << 4));
    }

    int s = 0, ph = 0;
    for (int kt = 0; kt < NKIT; ++kt) {
        mbar_wait(sb + SMEM_FULL + s * 8, ph);
        const uint32_t aBase = sb + SMEM_A + s * A_STAGE;
        const uint32_t bBase = sb + SMEM_B + s * B_STAGE;
#pragma unroll
        for (int j = 0; j < 4; ++j) {
            const uint32_t jsw = j * 32;   // k16 step = 32 bytes, XOR-safe
            uint32_t a[2][4];
            ldsm_x4(a[0], aBase + (a_off[0] ^ jsw));
            ldsm_x4(a[1], aBase + (a_off[1] ^ jsw));
#pragma unroll
            for (int ntp = 0; ntp < 4; ++ntp) {
                uint32_t b[4];
                ldsm_x4(b, bBase + (b_off[ntp] ^ jsw));
                mma16816(acc[0][2 * ntp + 0], a[0], b + 0);
                mma16816(acc[0][2 * ntp + 1], a[0], b + 2);
                mma16816(acc[1][2 * ntp + 0], a[1], b + 0);
                mma16816(acc[1][2 * ntp + 1], a[1], b + 2);
            }
        }
        __syncwarp();
        if (lid == 0) mbar_arrive(sb + SMEM_EMPTY + s * 8);
        if (++s == NST) { s = 0; ph ^= 1; }
    }

    // epilogue: bias + direct stores
    float* obase = out + (size_t)(m_base + warp_m * 32) * N_TOTAL + n_base +
                   warp_n * 64;
    const int r0 = lid >> 2;
    const int c0 = (lid & 3) * 2;
#pragma unroll
    for (int mt = 0; mt < 2; ++mt) {
#pragma unroll
        for (int nt = 0; nt < 8; ++nt) {
            int col = nt * 8 + c0;
            float b0 = sh_bias[warp_n * 64 + col];
            float b1 = sh_bias[warp_n * 64 + col + 1];
            float2 v0 = {acc[mt][nt][0] + b0, acc[mt][nt][1] + b1};
            float2 v1 = {acc[mt][nt][2] + b0, acc[mt][nt][3] + b1};
            *reinterpret_cast<float2*>(obase + (size_t)(mt * 16 + r0) * N_TOTAL + col) = v0;
            *reinterpret_cast<float2*>(obase + (size_t)(mt * 16 + r0 + 8) * N_TOTAL + col) = v1;
        }
    }
}

// ---------------------------------------------------------------------------
// Host
// ---------------------------------------------------------------------------
typedef CUresult (*PFN_encodeTiled)(
    CUtensorMap*, CUtensorMapDataType, cuuint32_t, void*,
    const cuuint64_t*, const cuuint64_t*, const cuuint32_t*, const cuuint32_t*,
    CUtensorMapInterleave, CUtensorMapSwizzle, CUtensorMapL2promotion,
    CUtensorMapFloatOOBfill);

extern "C" void kernel_launch(void* const* d_in, const int* in_sizes, int n_in,
                              void* d_out, int out_size) {
    const float* x    = (const float*)d_in[0];
    const float* Wqkv = (const float*)d_in[1];
    const float* bqkv = (const float*)d_in[2];
    const float* Waq  = (const float*)d_in[3];
    const float* Wbq  = (const float*)d_in[4];
    const float* Wav  = (const float*)d_in[5];
    const float* Wbv  = (const float*)d_in[6];
    float* out = (float*)d_out;

    prep_kernel<<<CONV_BLOCKS + FUSE_BLOCKS, 256>>>(
        (const float4*)x, (const float4*)Wqkv, (const float4*)Waq, Wbq,
        (const float4*)Wav, Wbv);

    void* xh_ptr = nullptr;
    void* wh_ptr = nullptr;
    cudaGetSymbolAddress(&xh_ptr, g_xh);
    cudaGetSymbolAddress(&wh_ptr, g_wh);

    void* fp = nullptr;
    cudaDriverEntryPointQueryResult qr;
#if CUDART_VERSION >= 12050
    cudaGetDriverEntryPointByVersion("cuTensorMapEncodeTiled", &fp, 12000,
                                     cudaEnableDefault, &qr);
#else
    cudaGetDriverEntryPoint("cuTensorMapEncodeTiled", &fp, cudaEnableDefault, &qr);
#endif
    PFN_encodeTiled encode = (PFN_encodeTiled)fp;

    CUtensorMap tmA, tmB;
    {
        cuuint64_t dims[2]   = {(cuuint64_t)K_TOTAL, (cuuint64_t)M_TOTAL};
        cuuint64_t stride[1] = {(cuuint64_t)K_TOTAL * 2};
        cuuint32_t box[2]    = {KCHUNK, TILE_M};
        cuuint32_t es[2]     = {1, 1};
        encode(&tmA, CU_TENSOR_MAP_DATA_TYPE_FLOAT16, 2, xh_ptr, dims, stride, box,
               es, CU_TENSOR_MAP_INTERLEAVE_NONE, CU_TENSOR_MAP_SWIZZLE_128B,
               CU_TENSOR_MAP_L2_PROMOTION_L2_128B, CU_TENSOR_MAP_FLOAT_OOB_FILL_NONE);
    }
    {
        cuuint64_t dims[2]   = {(cuuint64_t)K_TOTAL, (cuuint64_t)N_TOTAL};
        cuuint64_t stride[1] = {(cuuint64_t)K_TOTAL * 2};
        cuuint32_t box[2]    = {KCHUNK, TILE_N};
        cuuint32_t es[2]     = {1, 1};
        encode(&tmB, CU_TENSOR_MAP_DATA_TYPE_FLOAT16, 2, wh_ptr, dims, stride, box,
               es, CU_TENSOR_MAP_INTERLEAVE_NONE, CU_TENSOR_MAP_SWIZZLE_128B,
               CU_TENSOR_MAP_L2_PROMOTION_L2_128B, CU_TENSOR_MAP_FLOAT_OOB_FILL_NONE);
    }

    cudaFuncSetAttribute(gemm_f16_kernel,
                         cudaFuncAttributeMaxDynamicSharedMemorySize, SMEM_TOTAL);

    dim3 grid(N_TOTAL / TILE_N, M_TOTAL / TILE_M, 1);   // (24, 128)
    gemm_f16_kernel<<<grid, 288, SMEM_TOTAL>>>(tmA, tmB, bqkv, out);
}

// round 17
// speedup vs baseline: 1.2405x; 1.0008x over previous
#include <cuda.h>
#include <cuda_runtime.h>
#include <cuda_fp16.h>
#include <cstdint>

// ---------------------------------------------------------------------------
// out[16384,3072] = x[16384,1024] @ W_eff^T + b
// W_eff = W_qkv; rows[0:1024) += W_b_q@W_a_q; rows[2048:3072) += W_b_v@W_a_v
// Fold LoRA into weights (fp32), convert x & W_eff to fp16, one GEMM.
// GEMM: known-good round-4 config — 128x128 tile, 2 CTAs/SM, 9 warps
// (8 compute, warp tile 32x64; 1 TMA producer), 3-stage TMA pipeline.
// Legacy mma.sync (HMMA) — measured at the HMMA issue ceiling.
// Pre-kernels merged into one launch (conv x->fp16 + LoRA-fold W->fp16).
// ---------------------------------------------------------------------------

#define M_TOTAL 16384
#define N_TOTAL 3072
#define K_TOTAL 1024
#define TILE_M 128
#define TILE_N 128
#define KCHUNK 64                       // fp16 elems per stage = 128B (SW128 row)
#define NKIT   (K_TOTAL / KCHUNK)       // 16
#define NST    3
#define A_STAGE 16384                   // TILE_M * 128B
#define B_STAGE 16384                   // TILE_N * 128B

#define SMEM_FULL  16                   // 3 x 8B
#define SMEM_EMPTY 48                   // 3 x 8B
#define SMEM_BIAS  128                  // 128 floats
#define SMEM_A     1024
#define SMEM_B     (SMEM_A + NST * A_STAGE)     // 50176
#define SMEM_TOTAL (SMEM_B + NST * B_STAGE)     // 99328 -> 2 CTAs/SM

// merged pre-kernel geometry
#define CONV_BLOCKS 8192                // (M*K/8)/256
#define FUSE_BLOCKS 3072                // (N*K/4)/256

// fp16 scratch (static device arrays are allowed; cudaMalloc is not)
__device__ __align__(1024) __half g_xh[(size_t)M_TOTAL * K_TOTAL];
__device__ __align__(1024) __half g_wh[(size_t)N_TOTAL * K_TOTAL];

// ---------------------------------------------------------------------------
// PTX helpers (all plain sm_90-level, compile at compute_103)
// ---------------------------------------------------------------------------
__device__ __forceinline__ uint32_t smem_u32(const void* p) {
    uint32_t a;
    asm("{ .reg .u64 t; cvta.to.shared.u64 t, %1; cvt.u32.u64 %0, t; }"
        : "=r"(a) : "l"(p));
    return a;
}
__device__ __forceinline__ uint32_t elect_one() {
    uint32_t pred;
    asm volatile(
        "{\n\t.reg .pred p;\n\telect.sync _|p, 0xFFFFFFFF;\n\t"
        "selp.b32 %0, 1, 0, p;\n\t}" : "=r"(pred));
    return pred;
}
__device__ __forceinline__ void mbar_init(uint32_t m, uint32_t c) {
    asm volatile("mbarrier.init.shared.b64 [%0], %1;" :: "r"(m), "r"(c) : "memory");
}
__device__ __forceinline__ void mbar_expect_tx(uint32_t m, uint32_t bytes) {
    asm volatile("mbarrier.arrive.expect_tx.shared.b64 _, [%0], %1;"
                 :: "r"(m), "r"(bytes) : "memory");
}
__device__ __forceinline__ void mbar_arrive(uint32_t m) {
    asm volatile("mbarrier.arrive.shared.b64 _, [%0];" :: "r"(m) : "memory");
}
__device__ __forceinline__ void mbar_wait(uint32_t m, uint32_t phase) {
    uint32_t done = 0;
    while (!done) {
        asm volatile(
            "{\n\t.reg .pred p;\n\t"
            "mbarrier.try_wait.parity.acquire.cta.shared::cta.b64 p, [%1], %2, 0x989680;\n\t"
            "selp.b32 %0, 1, 0, p;\n\t}"
            : "=r"(done) : "r"(m), "r"(phase) : "memory");
    }
}
__device__ __forceinline__ void tma_load_2d(uint32_t dst, const void* map,
                                            int cx, int cy, uint32_t mbar) {
    asm volatile(
        "cp.async.bulk.tensor.2d.shared::cta.global.tile.mbarrier::complete_tx::bytes "
        "[%0], [%1, {%2, %3}], [%4];"
        :: "r"(dst), "l"(map), "r"(cx), "r"(cy), "r"(mbar) : "memory");
}
__device__ __forceinline__ void ldsm_x4(uint32_t* r, uint32_t addr) {
    asm volatile("ldmatrix.sync.aligned.m8n8.x4.shared.b16 {%0,%1,%2,%3}, [%4];"
                 : "=r"(r[0]), "=r"(r[1]), "=r"(r[2]), "=r"(r[3]) : "r"(addr));
}
__device__ __forceinline__ void mma16816(float* c, const uint32_t* a,
                                         const uint32_t* b) {
    asm volatile(
        "mma.sync.aligned.m16n8k16.row.col.f32.f16.f16.f32 "
        "{%0,%1,%2,%3}, {%4,%5,%6,%7}, {%8,%9}, {%0,%1,%2,%3};"
        : "+f"(c[0]), "+f"(c[1]), "+f"(c[2]), "+f"(c[3])
        : "r"(a[0]), "r"(a[1]), "r"(a[2]), "r"(a[3]), "r"(b[0]), "r"(b[1]));
}

// ---------------------------------------------------------------------------
// Merged pre-kernel: blocks [0, CONV_BLOCKS) convert x fp32->fp16 (8/thread);
// blocks [CONV_BLOCKS, CONV_BLOCKS+FUSE_BLOCKS) build W_eff fp16 (4/thread).
// ---------------------------------------------------------------------------
__device__ __forceinline__ uint32_t h2_bits(__half2 h) {
    return *reinterpret_cast<uint32_t*>(&h);
}

__global__ void prep_kernel(const float4* __restrict__ x,
                            const float4* __restrict__ Wqkv4,
                            const float4* __restrict__ Waq4,
                            const float* __restrict__ Wbq,
                            const float4* __restrict__ Wav4,
                            const float* __restrict__ Wbv) {
    if (blockIdx.x < CONV_BLOCKS) {
        int i = blockIdx.x * 256 + threadIdx.x;      // M*K/8 threads
        float4 v0 = x[2 * i + 0];
        float4 v1 = x[2 * i + 1];
        uint4 o;
        o.x = h2_bits(__floats2half2_rn(v0.x, v0.y));
        o.y = h2_bits(__floats2half2_rn(v0.z, v0.w));
        o.z = h2_bits(__floats2half2_rn(v1.x, v1.y));
        o.w = h2_bits(__floats2half2_rn(v1.z, v1.w));
        reinterpret_cast<uint4*>(g_xh)[i] = o;
    } else {
        int idx4 = (blockIdx.x - CONV_BLOCKS) * 256 + threadIdx.x;  // N*K/4
        int n = idx4 >> 8;               // 256 float4 per row (K=1024)
        int k4 = idx4 & 255;
        float4 acc = Wqkv4[idx4];
        if (n < 1024) {
#pragma unroll
            for (int r = 0; r < 16; ++r) {
                float br = Wbq[n * 16 + r];
                float4 wa = Waq4[r * 256 + k4];
                acc.x += br * wa.x; acc.y += br * wa.y;
                acc.z += br * wa.z; acc.w += br * wa.w;
            }
        } else if (n >= 2048) {
            int nn = n - 2048;
#pragma unroll
            for (int r = 0; r < 16; ++r) {
                float br = Wbv[nn * 16 + r];
                float4 wa = Wav4[r * 256 + k4];
                acc.x += br * wa.x; acc.y += br * wa.y;
                acc.z += br * wa.z; acc.w += br * wa.w;
            }
        }
        uint2 o;
        o.x = h2_bits(__floats2half2_rn(acc.x, acc.y));
        o.y = h2_bits(__floats2half2_rn(acc.z, acc.w));
        reinterpret_cast<uint2*>(g_wh)[idx4] = o;
    }
}

// ---------------------------------------------------------------------------
// Main GEMM (known-good round-4 config): 128x128 tile, 3-stage TMA pipeline,
// 9 warps (8 compute in 4(m)x2(n) grid, warp tile 32x64; warp 8 = producer)
// grid = (N/128, M/128) = (24, 128), 2 CTAs/SM
// ---------------------------------------------------------------------------
__global__ void __launch_bounds__(288, 2)
gemm_f16_kernel(const __grid_constant__ CUtensorMap tmA,
                const __grid_constant__ CUtensorMap tmB,
                const float* __restrict__ bias,
                float* __restrict__ out) {
    extern __shared__ __align__(1024) char smem[];
    const uint32_t sb = smem_u32(smem);
    const int tid = threadIdx.x;
    const int wid = tid >> 5;
    const int lid = tid & 31;
    const int n_base = blockIdx.x * TILE_N;
    const int m_base = blockIdx.y * TILE_M;

    if (tid == 0) {
#pragma unroll
        for (int s = 0; s < NST; ++s) {
            mbar_init(sb + SMEM_FULL + s * 8, 1);
            mbar_init(sb + SMEM_EMPTY + s * 8, 8);
        }
    }
    float* sh_bias = reinterpret_cast<float*>(smem + SMEM_BIAS);
    if (tid < TILE_N) sh_bias[tid] = bias[n_base + tid];
    __syncthreads();

    // ---- producer: warp 8, one elected lane ----
    if (wid == 8) {
        if (elect_one()) {
            int s = 0, ph = 1;                      // phase 1: first waits pass
            for (int kt = 0; kt < NKIT; ++kt) {
                mbar_wait(sb + SMEM_EMPTY + s * 8, ph);
                mbar_expect_tx(sb + SMEM_FULL + s * 8, A_STAGE + B_STAGE);
                tma_load_2d(sb + SMEM_A + s * A_STAGE, &tmA, kt * KCHUNK, m_base,
                            sb + SMEM_FULL + s * 8);
                tma_load_2d(sb + SMEM_B + s * B_STAGE, &tmB, kt * KCHUNK, n_base,
                            sb + SMEM_FULL + s * 8);
                if (++s == NST) { s = 0; ph ^= 1; }
            }
        }
        return;
    }

    // ---- compute warps 0..7: warp grid 4(m) x 2(n), warp tile 32x64 ----
    const int warp_m = wid & 3;
    const int warp_n = wid >> 2;
    const int grp = lid >> 3;
    const int lr = lid & 7;

    float acc[2][8][4];
#pragma unroll
    for (int mt = 0; mt < 2; ++mt)
#pragma unroll
        for (int nt = 0; nt < 8; ++nt)
#pragma unroll
            for (int q = 0; q < 4; ++q) acc[mt][nt][q] = 0.f;

    // swizzled per-lane base offsets within a stage (j=0)
    uint32_t a_off[2];
#pragma unroll
    for (int mt = 0; mt < 2; ++mt) {
        int row = warp_m * 32 + mt * 16 + (grp & 1) * 8 + lr;
        int colb = (grp >> 1) * 16;
        a_off[mt] = row * 128 + (colb ^ ((row & 7) << 4));
    }
    uint32_t b_off[4];
#pragma unroll
    for (int ntp = 0; ntp < 4; ++ntp) {
        int nrow = warp_n * 64 + ntp * 16 + (grp >> 1) * 8 + lr;
        int colb = (grp & 1) * 16;
        b_off[ntp] = nrow * 128 + (colb ^ ((nrow & 7) << 4));
    }

    int s = 0, ph = 0;
    for (int kt = 0; kt < NKIT; ++kt) {
        mbar_wait(sb + SMEM_FULL + s * 8, ph);
        const uint32_t aBase = sb + SMEM_A + s * A_STAGE;
        const uint32_t bBase = sb + SMEM_B + s * B_STAGE;
#pragma unroll
        for (int j = 0; j < 4; ++j) {
            const uint32_t jsw = j * 32;   // k16 step = 32 bytes, XOR-safe
            uint32_t a[2][4];
            ldsm_x4(a[0], aBase + (a_off[0] ^ jsw));
            ldsm_x4(a[1], aBase + (a_off[1] ^ jsw));
#pragma unroll
            for (int ntp = 0; ntp < 4; ++ntp) {
                uint32_t b[4];
                ldsm_x4(b, bBase + (b_off[ntp] ^ jsw));
                mma16816(acc[0][2 * ntp + 0], a[0], b + 0);
                mma16816(acc[0][2 * ntp + 1], a[0], b + 2);
                mma16816(acc[1][2 * ntp + 0], a[1], b + 0);
                mma16816(acc[1][2 * ntp + 1], a[1], b + 2);
            }
        }
        __syncwarp();
        if (lid == 0) mbar_arrive(sb + SMEM_EMPTY + s * 8);
        if (++s == NST) { s = 0; ph ^= 1; }
    }

    // epilogue: bias + direct stores
    float* obase = out + (size_t)(m_base + warp_m * 32) * N_TOTAL + n_base +
                   warp_n * 64;
    const int r0 = lid >> 2;
    const int c0 = (lid & 3) * 2;
#pragma unroll
    for (int mt = 0; mt < 2; ++mt) {
#pragma unroll
        for (int nt = 0; nt < 8; ++nt) {
            int col = nt * 8 + c0;
            float b0 = sh_bias[warp_n * 64 + col];
            float b1 = sh_bias[warp_n * 64 + col + 1];
            float2 v0 = {acc[mt][nt][0] + b0, acc[mt][nt][1] + b1};
            float2 v1 = {acc[mt][nt][2] + b0, acc[mt][nt][3] + b1};
            *reinterpret_cast<float2*>(obase + (size_t)(mt * 16 + r0) * N_TOTAL + col) = v0;
            *reinterpret_cast<float2*>(obase + (size_t)(mt * 16 + r0 + 8) * N_TOTAL + col) = v1;
        }
    }
}

// ---------------------------------------------------------------------------
// Host
// ---------------------------------------------------------------------------
typedef CUresult (*PFN_encodeTiled)(
    CUtensorMap*, CUtensorMapDataType, cuuint32_t, void*,
    const cuuint64_t*, const cuuint64_t*, const cuuint32_t*, const cuuint32_t*,
    CUtensorMapInterleave, CUtensorMapSwizzle, CUtensorMapL2promotion,
    CUtensorMapFloatOOBfill);

extern "C" void kernel_launch(void* const* d_in, const int* in_sizes, int n_in,
                              void* d_out, int out_size) {
    const float* x    = (const float*)d_in[0];
    const float* Wqkv = (const float*)d_in[1];
    const float* bqkv = (const float*)d_in[2];
    const float* Waq  = (const float*)d_in[3];
    const float* Wbq  = (const float*)d_in[4];
    const float* Wav  = (const float*)d_in[5];
    const float* Wbv  = (const float*)d_in[6];
    float* out = (float*)d_out;

    prep_kernel<<<CONV_BLOCKS + FUSE_BLOCKS, 256>>>(
        (const float4*)x, (const float4*)Wqkv, (const float4*)Waq, Wbq,
        (const float4*)Wav, Wbv);

    void* xh_ptr = nullptr;
    void* wh_ptr = nullptr;
    cudaGetSymbolAddress(&xh_ptr, g_xh);
    cudaGetSymbolAddress(&wh_ptr, g_wh);

    void* fp = nullptr;
    cudaDriverEntryPointQueryResult qr;
#if CUDART_VERSION >= 12050
    cudaGetDriverEntryPointByVersion("cuTensorMapEncodeTiled", &fp, 12000,
                                     cudaEnableDefault, &qr);
#else
    cudaGetDriverEntryPoint("cuTensorMapEncodeTiled", &fp, cudaEnableDefault, &qr);
#endif
    PFN_encodeTiled encode = (PFN_encodeTiled)fp;

    CUtensorMap tmA, tmB;
    {
        cuuint64_t dims[2]   = {(cuuint64_t)K_TOTAL, (cuuint64_t)M_TOTAL};
        cuuint64_t stride[1] = {(cuuint64_t)K_TOTAL * 2};
        cuuint32_t box[2]    = {KCHUNK, TILE_M};
        cuuint32_t es[2]     = {1, 1};
        encode(&tmA, CU_TENSOR_MAP_DATA_TYPE_FLOAT16, 2, xh_ptr, dims, stride, box,
               es, CU_TENSOR_MAP_INTERLEAVE_NONE, CU_TENSOR_MAP_SWIZZLE_128B,
               CU_TENSOR_MAP_L2_PROMOTION_L2_128B, CU_TENSOR_MAP_FLOAT_OOB_FILL_NONE);
    }
    {
        cuuint64_t dims[2]   = {(cuuint64_t)K_TOTAL, (cuuint64_t)N_TOTAL};
        cuuint64_t stride[1] = {(cuuint64_t)K_TOTAL * 2};
        cuuint32_t box[2]    = {KCHUNK, TILE_N};
        cuuint32_t es[2]     = {1, 1};
        encode(&tmB, CU_TENSOR_MAP_DATA_TYPE_FLOAT16, 2, wh_ptr, dims, stride, box,
               es, CU_TENSOR_MAP_INTERLEAVE_NONE, CU_TENSOR_MAP_SWIZZLE_128B,
               CU_TENSOR_MAP_L2_PROMOTION_L2_128B, CU_TENSOR_MAP_FLOAT_OOB_FILL_NONE);
    }

    cudaFuncSetAttribute(gemm_f16_kernel,
                         cudaFuncAttributeMaxDynamicSharedMemorySize, SMEM_TOTAL);

    dim3 grid(N_TOTAL / TILE_N, M_TOTAL / TILE_M, 1);   // (24, 128)
    gemm_f16_kernel<<<grid, 288, SMEM_TOTAL>>>(tmA, tmB, bqkv, out);
}